// round 4
// baseline (speedup 1.0000x reference)
#include <cuda_runtime.h>
#include <cuda_bf16.h>
#include <cstdint>

// Problem constants (fixed by the dataset)
#define NN 50000
#define EE 1600000
#define GG 512

// ---------------------------------------------------------------------------
// Device scratch (static; referenced only from device code; no allocations).
// float4 type guarantees 16B alignment.
// ---------------------------------------------------------------------------
__device__ int    g_deg[NN];
__device__ int    g_rowptr[NN + 1];
__device__ int    g_fill[NN];
__device__ int    g_col[EE];
__device__ int    g_gstart[GG + 1];
__device__ float4 g_agg4[(size_t)NN * 32];   // [N,128]
__device__ float4 g_h1_4[(size_t)NN * 32];   // [N,128]
__device__ float4 g_h2_4[(size_t)NN * 64];   // [N,256]
__device__ float4 g_y3_4[(size_t)NN * 32];   // [N,128]
__device__ float4 g_z3_4[(size_t)NN * 32];   // [N,128]

// Device-side buffer selector (5 => external x pointer)
__device__ __forceinline__ const float* buf_ptr(int sel, const float* x) {
    switch (sel) {
        case 0: return (const float*)g_agg4;
        case 1: return (const float*)g_h1_4;
        case 2: return (const float*)g_h2_4;
        case 3: return (const float*)g_y3_4;
        case 4: return (const float*)g_z3_4;
        default: return x;
    }
}
__device__ __forceinline__ float* out_ptr(int sel) {
    switch (sel) {
        case 0: return (float*)g_agg4;
        case 1: return (float*)g_h1_4;
        case 2: return (float*)g_h2_4;
        case 3: return (float*)g_y3_4;
        default: return (float*)g_z3_4;
    }
}

// ---------------------------------------------------------------------------
// CSR construction (indices are INT32: JAX default x64-off demotes int64)
// ---------------------------------------------------------------------------
__global__ void zero_deg_kernel() {
    int i = blockIdx.x * blockDim.x + threadIdx.x;
    if (i < NN) g_deg[i] = 0;
}

__global__ void count_kernel(const int* __restrict__ dst) {
    int e = blockIdx.x * blockDim.x + threadIdx.x;
    if (e < EE) {
        int d = dst[e];
        if (d >= 0 && d < NN) atomicAdd(&g_deg[d], 1);
    }
}

// Single-block exclusive scan over g_deg -> g_rowptr, g_fill (1024 threads)
__global__ void scan_kernel() {
    __shared__ int s[1024];
    __shared__ int carry_s;
    int tid = threadIdx.x;
    if (tid == 0) carry_s = 0;
    __syncthreads();
    for (int base = 0; base < NN; base += 1024) {
        int idx = base + tid;
        int v = (idx < NN) ? g_deg[idx] : 0;
        s[tid] = v;
        __syncthreads();
        #pragma unroll
        for (int off = 1; off < 1024; off <<= 1) {
            int t = (tid >= off) ? s[tid - off] : 0;
            __syncthreads();
            s[tid] += t;
            __syncthreads();
        }
        int excl = s[tid] - v;
        int c = carry_s;
        if (idx < NN) {
            g_rowptr[idx] = c + excl;
            g_fill[idx]   = c + excl;
        }
        int tot = s[1023];
        __syncthreads();
        if (tid == 0) carry_s = c + tot;
        __syncthreads();
    }
    if (threadIdx.x == 0) g_rowptr[NN] = carry_s;
}

__global__ void fill_kernel(const int* __restrict__ src,
                            const int* __restrict__ dst) {
    int e = blockIdx.x * blockDim.x + threadIdx.x;
    if (e < EE) {
        int d = dst[e];
        if (d >= 0 && d < NN) {
            int p = atomicAdd(&g_fill[d], 1);
            g_col[p] = src[e];
        }
    }
}

// ---------------------------------------------------------------------------
// Aggregation: g_agg[n] = sum over in-edges of feat[src], 128 features.
// One warp per node, float4 per lane, accumulation in registers.
// ---------------------------------------------------------------------------
__global__ void aggregate_kernel(const float* __restrict__ x, int feat_sel) {
    const float* feat = buf_ptr(feat_sel, x);
    int warp = (blockIdx.x * blockDim.x + threadIdx.x) >> 5;
    int lane = threadIdx.x & 31;
    if (warp >= NN) return;
    int s = g_rowptr[warp];
    int e = g_rowptr[warp + 1];
    float4 acc = make_float4(0.f, 0.f, 0.f, 0.f);
    for (int j = s; j < e; j++) {
        int c = g_col[j];
        float4 v = *(const float4*)&feat[(size_t)c * 128 + lane * 4];
        acc.x += v.x; acc.y += v.y; acc.z += v.z; acc.w += v.w;
    }
    g_agg4[(size_t)warp * 32 + lane] = acc;
}

// ---------------------------------------------------------------------------
// Fused dual-input SGEMM: C = act(A0@W0 [+ A1@W1] [+ bias])
// 128x128 block tile, 256 threads, 8x8 per thread, BK=16.
// A0/A1/C selected on-device from scratch symbols (a1_sel < 0 => absent).
// ---------------------------------------------------------------------------
__global__ void __launch_bounds__(256)
gemm_kernel(const float* __restrict__ x,
            int a0_sel, const float* __restrict__ W0, int K0,
            int a1_sel, const float* __restrict__ W1, int K1,
            const float* __restrict__ bias, int c_sel,
            int M, int Cout, int relu) {
    __shared__ float As[16][128];
    __shared__ float Bs[16][128];
    int tid  = threadIdx.x;
    int row0 = blockIdx.x * 128;
    int col0 = blockIdx.y * 128;
    int tm = (tid >> 4) << 3;   // 0..120 step 8
    int tn = (tid & 15) << 3;   // 0..120 step 8

    float acc[8][8];
    #pragma unroll
    for (int i = 0; i < 8; i++)
        #pragma unroll
        for (int j = 0; j < 8; j++) acc[i][j] = 0.f;

    #pragma unroll 1
    for (int seg = 0; seg < 2; seg++) {
        if (seg == 1 && a1_sel < 0) break;
        const float* A = buf_ptr(seg ? a1_sel : a0_sel, x);
        const float* W = seg ? W1 : W0;
        int K = seg ? K1 : K0;
        #pragma unroll 1
        for (int kt = 0; kt < K; kt += 16) {
            // stage A (transposed into As[k][m])
            #pragma unroll
            for (int i = 0; i < 2; i++) {
                int lin = tid * 2 + i;
                int ar = lin >> 2;          // 0..127
                int ak = (lin & 3) << 2;    // 0,4,8,12
                float4 v = make_float4(0.f, 0.f, 0.f, 0.f);
                int r = row0 + ar;
                if (r < M) v = *(const float4*)&A[(size_t)r * K + kt + ak];
                As[ak + 0][ar] = v.x;
                As[ak + 1][ar] = v.y;
                As[ak + 2][ar] = v.z;
                As[ak + 3][ar] = v.w;
            }
            // stage B
            #pragma unroll
            for (int i = 0; i < 2; i++) {
                int lin = tid * 2 + i;
                int bk = lin >> 5;          // 0..15
                int bn = (lin & 31) << 2;   // 0..124
                *(float4*)&Bs[bk][bn] =
                    *(const float4*)&W[(size_t)(kt + bk) * Cout + col0 + bn];
            }
            __syncthreads();
            #pragma unroll
            for (int k = 0; k < 16; k++) {
                float4 a0 = *(float4*)&As[k][tm];
                float4 a1 = *(float4*)&As[k][tm + 4];
                float4 b0 = *(float4*)&Bs[k][tn];
                float4 b1 = *(float4*)&Bs[k][tn + 4];
                float av[8] = {a0.x, a0.y, a0.z, a0.w, a1.x, a1.y, a1.z, a1.w};
                float bv[8] = {b0.x, b0.y, b0.z, b0.w, b1.x, b1.y, b1.z, b1.w};
                #pragma unroll
                for (int ii = 0; ii < 8; ii++)
                    #pragma unroll
                    for (int jj = 0; jj < 8; jj++)
                        acc[ii][jj] += av[ii] * bv[jj];
            }
            __syncthreads();
        }
    }

    float* C = out_ptr(c_sel);
    float bvals[8];
    #pragma unroll
    for (int j = 0; j < 8; j++)
        bvals[j] = bias ? bias[col0 + tn + j] : 0.f;

    #pragma unroll
    for (int i = 0; i < 8; i++) {
        int r = row0 + tm + i;
        if (r < M) {
            #pragma unroll
            for (int j = 0; j < 8; j++) {
                float v = acc[i][j] + bvals[j];
                if (relu) v = fmaxf(v, 0.f);
                acc[i][j] = v;
            }
            *(float4*)&C[(size_t)r * Cout + col0 + tn] =
                make_float4(acc[i][0], acc[i][1], acc[i][2], acc[i][3]);
            *(float4*)&C[(size_t)r * Cout + col0 + tn + 4] =
                make_float4(acc[i][4], acc[i][5], acc[i][6], acc[i][7]);
        }
    }
}

// ---------------------------------------------------------------------------
// Graph segment boundaries via binary search over sorted batch (int32)
// ---------------------------------------------------------------------------
__global__ void gstart_kernel(const int* __restrict__ batch) {
    int g = blockIdx.x * blockDim.x + threadIdx.x;
    if (g > GG) return;
    int lo = 0, hi = NN;
    while (lo < hi) {
        int mid = (lo + hi) >> 1;
        if (batch[mid] < g) lo = mid + 1; else hi = mid;
    }
    g_gstart[g] = lo;
}

// ---------------------------------------------------------------------------
// Pool (mean over graph) + 2-layer MLP head. One 128-thread block per graph.
// h3[n] = g_agg[n] + g_z3[n]  (agg3 of y3, plus h2@Wo3+br3)
// ---------------------------------------------------------------------------
__global__ void pool_head_kernel(const float* __restrict__ W1,
                                 const float* __restrict__ b1,
                                 const float* __restrict__ W2,
                                 const float* __restrict__ b2,
                                 float* __restrict__ out) {
    int g = blockIdx.x;
    int c = threadIdx.x;  // 0..127
    int s = g_gstart[g];
    int e = g_gstart[g + 1];
    const float* agg = (const float*)g_agg4;
    const float* z3  = (const float*)g_z3_4;
    float acc = 0.f;
    for (int n = s; n < e; n++)
        acc += agg[(size_t)n * 128 + c] + z3[(size_t)n * 128 + c];
    float cnt = (float)((e - s) > 1 ? (e - s) : 1);
    __shared__ float p[128];
    __shared__ float t[40];
    p[c] = acc / cnt;
    __syncthreads();
    if (c < 40) {
        float tt = b1[c];
        #pragma unroll 4
        for (int k = 0; k < 128; k++) tt += p[k] * W1[k * 40 + c];
        t[c] = tt;
    }
    __syncthreads();
    if (c < 10) {
        float o = b2[c];
        #pragma unroll
        for (int k = 0; k < 40; k++) o += t[k] * W2[k * 10 + c];
        out[g * 10 + c] = o;
    }
}

// ---------------------------------------------------------------------------
// Launch: ONLY kernel launches — no other CUDA API calls of any kind.
// ---------------------------------------------------------------------------
extern "C" void kernel_launch(void* const* d_in, const int* in_sizes, int n_in,
                              void* d_out, int out_size) {
    const float* x     = (const float*)d_in[0];
    const int*   ei    = (const int*)d_in[1];    // int32 (JAX x64 disabled)
    const int*   batch = (const int*)d_in[2];    // int32
    const float* Wr1 = (const float*)d_in[3];
    const float* br1 = (const float*)d_in[4];
    const float* Wo1 = (const float*)d_in[5];
    const float* Wr2 = (const float*)d_in[6];
    const float* br2 = (const float*)d_in[7];
    const float* Wo2 = (const float*)d_in[8];
    const float* Wr3 = (const float*)d_in[9];
    const float* br3 = (const float*)d_in[10];
    const float* Wo3 = (const float*)d_in[11];
    const float* W1  = (const float*)d_in[12];
    const float* b1  = (const float*)d_in[13];
    const float* W2  = (const float*)d_in[14];
    const float* b2  = (const float*)d_in[15];
    float* out = (float*)d_out;

    const int* srcp = ei;
    const int* dstp = ei + EE;

    const int EB = (EE + 255) / 256;
    const int AGGB = (NN * 32 + 255) / 256;
    dim3 g1((NN + 127) / 128, 1);
    dim3 g2((NN + 127) / 128, 2);

    // CSR build
    zero_deg_kernel<<<(NN + 255) / 256, 256>>>();
    count_kernel<<<EB, 256>>>(dstp);
    scan_kernel<<<1, 1024>>>();
    fill_kernel<<<EB, 256>>>(srcp, dstp);
    gstart_kernel<<<1, 1024>>>(batch);

    // Layer 1: agg = A(x); h1 = relu(agg@Wr1 + x@Wo1 + br1)
    aggregate_kernel<<<AGGB, 256>>>(x, 5);
    gemm_kernel<<<g1, 256>>>(x, 0, Wr1, 128, 5, Wo1, 128, br1, 1, NN, 128, 1);

    // Layer 2: agg = A(h1); h2 = relu(agg@Wr2 + h1@Wo2 + br2)
    aggregate_kernel<<<AGGB, 256>>>(x, 1);
    gemm_kernel<<<g2, 256>>>(x, 0, Wr2, 128, 1, Wo2, 128, br2, 2, NN, 256, 1);

    // Layer 3 (matmul-first): y3 = h2@Wr3; z3 = h2@Wo3 + br3; agg = A(y3)
    gemm_kernel<<<g1, 256>>>(x, 2, Wr3, 256, -1, nullptr, 0, nullptr, 3, NN, 128, 0);
    gemm_kernel<<<g1, 256>>>(x, 2, Wo3, 256, -1, nullptr, 0, br3, 4, NN, 128, 0);
    aggregate_kernel<<<AGGB, 256>>>(x, 3);

    // Pool + head
    pool_head_kernel<<<GG, 128>>>(W1, b1, W2, b2, out);
}

// round 5
// speedup vs baseline: 1.9624x; 1.9624x over previous
#include <cuda_runtime.h>
#include <cuda_bf16.h>
#include <cstdint>

// Problem constants (fixed by the dataset)
#define NN 50000
#define EE 1600000
#define GG 512

// ---------------------------------------------------------------------------
// Device scratch (static; referenced only from device code; no allocations).
// ---------------------------------------------------------------------------
__device__ int    g_deg[NN];
__device__ int    g_rowptr[NN + 1];
__device__ int    g_fill[NN];
__device__ int    g_col[EE];
__device__ int    g_gstart[GG + 1];
__device__ float4 g_agg4[(size_t)NN * 32];   // [N,128]
__device__ float4 g_h1_4[(size_t)NN * 32];   // [N,128]
__device__ float4 g_h2_4[(size_t)NN * 64];   // [N,256]
__device__ float4 g_y3_4[(size_t)NN * 32];   // [N,128]
__device__ float4 g_z3_4[(size_t)NN * 32];   // [N,128]

__device__ __forceinline__ const float* buf_ptr(int sel, const float* x) {
    switch (sel) {
        case 0: return (const float*)g_agg4;
        case 1: return (const float*)g_h1_4;
        case 2: return (const float*)g_h2_4;
        case 3: return (const float*)g_y3_4;
        case 4: return (const float*)g_z3_4;
        default: return x;
    }
}
__device__ __forceinline__ float* out_ptr(int sel) {
    switch (sel) {
        case 0: return (float*)g_agg4;
        case 1: return (float*)g_h1_4;
        case 2: return (float*)g_h2_4;
        case 3: return (float*)g_y3_4;
        default: return (float*)g_z3_4;
    }
}

// ---------------------------------------------------------------------------
// CSR construction (int32 indices)
// ---------------------------------------------------------------------------
__global__ void zero_deg_kernel() {
    int i = blockIdx.x * blockDim.x + threadIdx.x;
    if (i < NN) g_deg[i] = 0;
}

__global__ void count_kernel(const int* __restrict__ dst) {
    int e = blockIdx.x * blockDim.x + threadIdx.x;
    if (e < EE) {
        int d = dst[e];
        if (d >= 0 && d < NN) atomicAdd(&g_deg[d], 1);
    }
}

// Single-block shuffle-based exclusive scan over g_deg -> g_rowptr, g_fill
__global__ void scan_kernel() {
    __shared__ int wsum[32];
    __shared__ int carry_s;
    int tid = threadIdx.x;
    int lane = tid & 31, wid = tid >> 5;
    if (tid == 0) carry_s = 0;
    __syncthreads();
    for (int base = 0; base < NN; base += 1024) {
        int idx = base + tid;
        int v = (idx < NN) ? g_deg[idx] : 0;
        int sc = v;  // inclusive warp scan
        #pragma unroll
        for (int o = 1; o < 32; o <<= 1) {
            int t = __shfl_up_sync(0xFFFFFFFFu, sc, o);
            if (lane >= o) sc += t;
        }
        if (lane == 31) wsum[wid] = sc;
        __syncthreads();
        if (wid == 0) {
            int w = wsum[lane];
            int ws = w;
            #pragma unroll
            for (int o = 1; o < 32; o <<= 1) {
                int t = __shfl_up_sync(0xFFFFFFFFu, ws, o);
                if (lane >= o) ws += t;
            }
            wsum[lane] = ws - w;  // exclusive warp offsets
        }
        __syncthreads();
        int excl = carry_s + wsum[wid] + sc - v;
        if (idx < NN) {
            g_rowptr[idx] = excl;
            g_fill[idx]   = excl;
        }
        __syncthreads();
        if (tid == 1023) carry_s = excl + v;
        __syncthreads();
    }
    if (threadIdx.x == 0) g_rowptr[NN] = carry_s;
}

__global__ void fill_kernel(const int* __restrict__ src,
                            const int* __restrict__ dst) {
    int e = blockIdx.x * blockDim.x + threadIdx.x;
    if (e < EE) {
        int d = dst[e];
        if (d >= 0 && d < NN) {
            int p = atomicAdd(&g_fill[d], 1);
            g_col[p] = src[e];
        }
    }
}

// ---------------------------------------------------------------------------
// Aggregation: g_agg[n] = sum over in-edges of feat[src], 128 features.
// ---------------------------------------------------------------------------
__global__ void aggregate_kernel(const float* __restrict__ x, int feat_sel) {
    const float* feat = buf_ptr(feat_sel, x);
    int warp = (blockIdx.x * blockDim.x + threadIdx.x) >> 5;
    int lane = threadIdx.x & 31;
    if (warp >= NN) return;
    int s = g_rowptr[warp];
    int e = g_rowptr[warp + 1];
    float4 acc = make_float4(0.f, 0.f, 0.f, 0.f);
    for (int j = s; j < e; j++) {
        int c = g_col[j];
        float4 v = *(const float4*)&feat[(size_t)c * 128 + lane * 4];
        acc.x += v.x; acc.y += v.y; acc.z += v.z; acc.w += v.w;
    }
    g_agg4[(size_t)warp * 32 + lane] = acc;
}

// ---------------------------------------------------------------------------
// tf32 tensor-core fused dual-input GEMM: C = act(A0@W0 [+ A1@W1] [+ bias])
// 128x128 tile, BK=32, 8 warps (4x2), warp tile 32x64 via m16n8k8 tf32 mma.
// ---------------------------------------------------------------------------
__device__ __forceinline__ float to_tf32(float x) {
    float r;
    asm("cvt.rna.tf32.f32 %0, %1;" : "=f"(r) : "f"(x));
    return r;
}

__device__ __forceinline__ void mma_tf32(float* c, const uint32_t* a,
                                         const uint32_t* b) {
    asm volatile(
        "mma.sync.aligned.m16n8k8.row.col.f32.tf32.tf32.f32 "
        "{%0,%1,%2,%3}, {%4,%5,%6,%7}, {%8,%9}, {%0,%1,%2,%3};"
        : "+f"(c[0]), "+f"(c[1]), "+f"(c[2]), "+f"(c[3])
        : "r"(a[0]), "r"(a[1]), "r"(a[2]), "r"(a[3]), "r"(b[0]), "r"(b[1]));
}

#define BM 128
#define BN 128
#define BK 32

__global__ void __launch_bounds__(256)
gemm_tc_kernel(const float* __restrict__ x,
               int a0_sel, const float* __restrict__ W0, int K0,
               int a1_sel, const float* __restrict__ W1, int K1,
               const float* __restrict__ bias, int c_sel,
               int M, int Cout, int relu) {
    __shared__ float As[BM][BK + 4];   // [m][k], 36-float rows (144B, 16B-aligned)
    __shared__ float Bs[BK][BN + 8];   // [k][n], 136-float rows (544B, 16B-aligned)
    int tid  = threadIdx.x;
    int wid  = tid >> 5, lane = tid & 31;
    int gid  = lane >> 2, tig = lane & 3;
    int wm   = wid & 3,  wn  = wid >> 2;   // 4x2 warp grid
    int row0 = blockIdx.x * BM;
    int col0 = blockIdx.y * BN;

    float acc[2][8][4];
    #pragma unroll
    for (int i = 0; i < 2; i++)
        #pragma unroll
        for (int j = 0; j < 8; j++)
            #pragma unroll
            for (int k = 0; k < 4; k++) acc[i][j][k] = 0.f;

    #pragma unroll 1
    for (int seg = 0; seg < 2; seg++) {
        if (seg == 1 && a1_sel < 0) break;
        const float* A = buf_ptr(seg ? a1_sel : a0_sel, x);
        const float* W = seg ? W1 : W0;
        int K = seg ? K1 : K0;
        #pragma unroll 1
        for (int kt = 0; kt < K; kt += BK) {
            // stage A tile [BM x BK] (tf32-converted at store)
            #pragma unroll
            for (int i = 0; i < 4; i++) {
                int lin = tid + i * 256;      // 0..1023
                int r   = lin >> 3;           // 0..127
                int c4  = (lin & 7) << 2;     // 0..28 step 4
                float4 v = make_float4(0.f, 0.f, 0.f, 0.f);
                int gr = row0 + r;
                if (gr < M) v = *(const float4*)&A[(size_t)gr * K + kt + c4];
                float4 cv = make_float4(to_tf32(v.x), to_tf32(v.y),
                                        to_tf32(v.z), to_tf32(v.w));
                *(float4*)&As[r][c4] = cv;
            }
            // stage B tile [BK x BN]
            #pragma unroll
            for (int i = 0; i < 4; i++) {
                int lin = tid + i * 256;
                int bk  = lin >> 5;           // 0..31
                int c4  = (lin & 31) << 2;    // 0..124 step 4
                float4 v = *(const float4*)&W[(size_t)(kt + bk) * Cout + col0 + c4];
                float4 cv = make_float4(to_tf32(v.x), to_tf32(v.y),
                                        to_tf32(v.z), to_tf32(v.w));
                *(float4*)&Bs[bk][c4] = cv;
            }
            __syncthreads();
            #pragma unroll
            for (int ks = 0; ks < 4; ks++) {
                int k0 = ks * 8;
                uint32_t af[2][4];
                #pragma unroll
                for (int mt = 0; mt < 2; mt++) {
                    int r = wm * 32 + mt * 16 + gid;
                    af[mt][0] = __float_as_uint(As[r    ][k0 + tig]);
                    af[mt][1] = __float_as_uint(As[r + 8][k0 + tig]);
                    af[mt][2] = __float_as_uint(As[r    ][k0 + tig + 4]);
                    af[mt][3] = __float_as_uint(As[r + 8][k0 + tig + 4]);
                }
                uint32_t bf[8][2];
                #pragma unroll
                for (int nt = 0; nt < 8; nt++) {
                    int c = wn * 64 + nt * 8 + gid;
                    bf[nt][0] = __float_as_uint(Bs[k0 + tig    ][c]);
                    bf[nt][1] = __float_as_uint(Bs[k0 + tig + 4][c]);
                }
                #pragma unroll
                for (int mt = 0; mt < 2; mt++)
                    #pragma unroll
                    for (int nt = 0; nt < 8; nt++)
                        mma_tf32(acc[mt][nt], af[mt], bf[nt]);
            }
            __syncthreads();
        }
    }

    float* C = out_ptr(c_sel);
    #pragma unroll
    for (int mt = 0; mt < 2; mt++) {
        #pragma unroll
        for (int half = 0; half < 2; half++) {
            int r = row0 + wm * 32 + mt * 16 + gid + half * 8;
            if (r < M) {
                #pragma unroll
                for (int nt = 0; nt < 8; nt++) {
                    int c = col0 + wn * 64 + nt * 8 + tig * 2;
                    float v0 = acc[mt][nt][half * 2 + 0];
                    float v1 = acc[mt][nt][half * 2 + 1];
                    if (bias) { v0 += bias[c]; v1 += bias[c + 1]; }
                    if (relu) { v0 = fmaxf(v0, 0.f); v1 = fmaxf(v1, 0.f); }
                    *(float2*)&C[(size_t)r * Cout + c] = make_float2(v0, v1);
                }
            }
        }
    }
}

// ---------------------------------------------------------------------------
// Graph segment boundaries via binary search over sorted batch (int32)
// ---------------------------------------------------------------------------
__global__ void gstart_kernel(const int* __restrict__ batch) {
    int g = blockIdx.x * blockDim.x + threadIdx.x;
    if (g > GG) return;
    int lo = 0, hi = NN;
    while (lo < hi) {
        int mid = (lo + hi) >> 1;
        if (batch[mid] < g) lo = mid + 1; else hi = mid;
    }
    g_gstart[g] = lo;
}

// ---------------------------------------------------------------------------
// Pool (mean over graph) + 2-layer MLP head. One 128-thread block per graph.
// h3[n] = g_agg[n] + g_z3[n]
// ---------------------------------------------------------------------------
__global__ void pool_head_kernel(const float* __restrict__ W1,
                                 const float* __restrict__ b1,
                                 const float* __restrict__ W2,
                                 const float* __restrict__ b2,
                                 float* __restrict__ out) {
    int g = blockIdx.x;
    int c = threadIdx.x;  // 0..127
    int s = g_gstart[g];
    int e = g_gstart[g + 1];
    const float* agg = (const float*)g_agg4;
    const float* z3  = (const float*)g_z3_4;
    float acc = 0.f;
    for (int n = s; n < e; n++)
        acc += agg[(size_t)n * 128 + c] + z3[(size_t)n * 128 + c];
    float cnt = (float)((e - s) > 1 ? (e - s) : 1);
    __shared__ float p[128];
    __shared__ float t[40];
    p[c] = acc / cnt;
    __syncthreads();
    if (c < 40) {
        float tt = b1[c];
        #pragma unroll 4
        for (int k = 0; k < 128; k++) tt += p[k] * W1[k * 40 + c];
        t[c] = tt;
    }
    __syncthreads();
    if (c < 10) {
        float o = b2[c];
        #pragma unroll
        for (int k = 0; k < 40; k++) o += t[k] * W2[k * 10 + c];
        out[g * 10 + c] = o;
    }
}

// ---------------------------------------------------------------------------
// Launch: ONLY kernel launches.
// ---------------------------------------------------------------------------
extern "C" void kernel_launch(void* const* d_in, const int* in_sizes, int n_in,
                              void* d_out, int out_size) {
    const float* x     = (const float*)d_in[0];
    const int*   ei    = (const int*)d_in[1];    // int32
    const int*   batch = (const int*)d_in[2];    // int32
    const float* Wr1 = (const float*)d_in[3];
    const float* br1 = (const float*)d_in[4];
    const float* Wo1 = (const float*)d_in[5];
    const float* Wr2 = (const float*)d_in[6];
    const float* br2 = (const float*)d_in[7];
    const float* Wo2 = (const float*)d_in[8];
    const float* Wr3 = (const float*)d_in[9];
    const float* br3 = (const float*)d_in[10];
    const float* Wo3 = (const float*)d_in[11];
    const float* W1  = (const float*)d_in[12];
    const float* b1  = (const float*)d_in[13];
    const float* W2  = (const float*)d_in[14];
    const float* b2  = (const float*)d_in[15];
    float* out = (float*)d_out;

    const int* srcp = ei;
    const int* dstp = ei + EE;

    const int EB = (EE + 255) / 256;
    const int AGGB = (NN * 32 + 255) / 256;
    dim3 g1((NN + 127) / 128, 1);
    dim3 g2((NN + 127) / 128, 2);

    // CSR build
    zero_deg_kernel<<<(NN + 255) / 256, 256>>>();
    count_kernel<<<EB, 256>>>(dstp);
    scan_kernel<<<1, 1024>>>();
    fill_kernel<<<EB, 256>>>(srcp, dstp);
    gstart_kernel<<<1, 1024>>>(batch);

    // Layer 1: agg = A(x); h1 = relu(agg@Wr1 + x@Wo1 + br1)
    aggregate_kernel<<<AGGB, 256>>>(x, 5);
    gemm_tc_kernel<<<g1, 256>>>(x, 0, Wr1, 128, 5, Wo1, 128, br1, 1, NN, 128, 1);

    // Layer 2: agg = A(h1); h2 = relu(agg@Wr2 + h1@Wo2 + br2)
    aggregate_kernel<<<AGGB, 256>>>(x, 1);
    gemm_tc_kernel<<<g2, 256>>>(x, 0, Wr2, 128, 1, Wo2, 128, br2, 2, NN, 256, 1);

    // Layer 3 (matmul-first): y3 = h2@Wr3; z3 = h2@Wo3 + br3; agg = A(y3)
    gemm_tc_kernel<<<g1, 256>>>(x, 2, Wr3, 256, -1, nullptr, 0, nullptr, 3, NN, 128, 0);
    gemm_tc_kernel<<<g1, 256>>>(x, 2, Wo3, 256, -1, nullptr, 0, br3, 4, NN, 128, 0);
    aggregate_kernel<<<AGGB, 256>>>(x, 3);

    // Pool + head
    pool_head_kernel<<<GG, 128>>>(W1, b1, W2, b2, out);
}